// round 15
// baseline (speedup 1.0000x reference)
#include <cuda_runtime.h>
#include <cuda_fp16.h>
#include <cstdint>

#define NN   20000
#define EE   320000
#define IND  128
#define HD   64
#define NH   4
#define QKVD 256   // NH * HD
#define NL   3
#define NG   128
#define NB   79    // scan blocks: ceil(NN/256)

// ---------------- scratch (device globals) ----------------------------------
__device__ float  g_h0[NN * HD];
__device__ float  g_h1[NN * HD];
__device__ float  g_q[NN * QKVD];
__device__ __half g_kh[NN * QKVD];
__device__ __half g_vh[NN * QKVD];
__device__ float  g_s[NN * HD];
__device__ int    g_cnt[NN];
__device__ int    g_rowptr[NN + 1];
__device__ int    g_cursor[NN];
__device__ int    g_srcs[EE];
__device__ int    g_bsum[128];
__device__ int    g_boff[128];
__device__ int    g_use32;   // 1 => edge_index/batch are int32, 0 => int64

__device__ __forceinline__ float* buf_sel(int s) {
    return s == 0 ? g_h0 : g_h1;
}

__device__ __forceinline__ int clampN(int i) {
    return i < 0 ? 0 : (i >= NN ? NN - 1 : i);
}

// ---------------- dtype detection -------------------------------------------
__global__ void k_detect(const void* __restrict__ ei) {
    const long long* p = (const long long*)ei;
    int t = threadIdx.x;           // 32 threads
    long long v = p[t];
    unsigned bad = __ballot_sync(0xffffffffu, v < 0 || v >= (long long)NN);
    if (t == 0) g_use32 = (bad != 0u) ? 1 : 0;
}

// ---------------- CSR build (counting sort by dst) --------------------------
__global__ void k_zero_cnt() {
    int i = blockIdx.x * blockDim.x + threadIdx.x;
    if (i < NN) g_cnt[i] = 0;
}

// 4 edges per thread, vectorized index loads
__global__ void k_count(const void* __restrict__ ei) {
    int e4 = blockIdx.x * blockDim.x + threadIdx.x;
    if (e4 < EE / 4) {
        int d[4];
        if (g_use32) {
            int4 dd = *((const int4*)ei + (EE + 4 * e4) / 4);
            d[0] = dd.x; d[1] = dd.y; d[2] = dd.z; d[3] = dd.w;
        } else {
            longlong2 a = *((const longlong2*)ei + (EE + 4 * e4) / 2);
            longlong2 b = *((const longlong2*)ei + (EE + 4 * e4) / 2 + 1);
            d[0] = (int)a.x; d[1] = (int)a.y; d[2] = (int)b.x; d[3] = (int)b.y;
        }
        #pragma unroll
        for (int j = 0; j < 4; j++) atomicAdd(&g_cnt[clampN(d[j])], 1);
    }
}

__global__ void k_scan1() {
    __shared__ int ws[8];
    int t = threadIdx.x, lane = t & 31, wid = t >> 5;
    int i = blockIdx.x * 256 + t;
    int v = (i < NN) ? g_cnt[i] : 0;
    int s = v;
    #pragma unroll
    for (int d = 16; d > 0; d >>= 1) s += __shfl_xor_sync(0xffffffffu, s, d);
    if (lane == 0) ws[wid] = s;
    __syncthreads();
    if (t < 8) {
        int x = ws[t];
        #pragma unroll
        for (int d = 4; d > 0; d >>= 1) x += __shfl_xor_sync(0xffu, x, d);
        if (t == 0) g_bsum[blockIdx.x] = x;
    }
}

__global__ void k_scan2() {
    __shared__ int wsum[4];
    int t = threadIdx.x, lane = t & 31, wid = t >> 5;
    int v = (t < NB) ? g_bsum[t] : 0;
    int incl = v;
    #pragma unroll
    for (int d = 1; d < 32; d <<= 1) {
        int nb = __shfl_up_sync(0xffffffffu, incl, d);
        if (lane >= d) incl += nb;
    }
    if (lane == 31) wsum[wid] = incl;
    __syncthreads();
    int off = 0;
    for (int w = 0; w < wid; w++) off += wsum[w];
    if (t < NB) g_boff[t] = off + incl - v;
}

__global__ void k_scan3() {
    __shared__ int wincl[8];
    int t = threadIdx.x, lane = t & 31, wid = t >> 5;
    int i = blockIdx.x * 256 + t;
    int v = (i < NN) ? g_cnt[i] : 0;
    int incl = v;
    #pragma unroll
    for (int d = 1; d < 32; d <<= 1) {
        int nb = __shfl_up_sync(0xffffffffu, incl, d);
        if (lane >= d) incl += nb;
    }
    if (lane == 31) wincl[wid] = incl;
    __syncthreads();
    int woff = 0;
    for (int w = 0; w < wid; w++) woff += wincl[w];
    int excl = g_boff[blockIdx.x] + woff + incl - v;
    if (i < NN) {
        g_cursor[i] = excl;
        g_rowptr[i + 1] = excl + v;
        if (i == 0) g_rowptr[0] = 0;
    }
}

// 4 edges per thread, vectorized index loads
__global__ void k_scatter(const void* __restrict__ ei) {
    int e4 = blockIdx.x * blockDim.x + threadIdx.x;
    if (e4 < EE / 4) {
        int d[4], s[4];
        if (g_use32) {
            int4 dd = *((const int4*)ei + (EE + 4 * e4) / 4);
            int4 ss = *((const int4*)ei + (4 * e4) / 4);
            d[0] = dd.x; d[1] = dd.y; d[2] = dd.z; d[3] = dd.w;
            s[0] = ss.x; s[1] = ss.y; s[2] = ss.z; s[3] = ss.w;
        } else {
            longlong2 a = *((const longlong2*)ei + (EE + 4 * e4) / 2);
            longlong2 b = *((const longlong2*)ei + (EE + 4 * e4) / 2 + 1);
            longlong2 c = *((const longlong2*)ei + (4 * e4) / 2);
            longlong2 e = *((const longlong2*)ei + (4 * e4) / 2 + 1);
            d[0] = (int)a.x; d[1] = (int)a.y; d[2] = (int)b.x; d[3] = (int)b.y;
            s[0] = (int)c.x; s[1] = (int)c.y; s[2] = (int)e.x; s[3] = (int)e.y;
        }
        #pragma unroll
        for (int j = 0; j < 4; j++) {
            int pos = atomicAdd(&g_cursor[clampN(d[j])], 1);
            g_srcs[pos] = clampN(s[j]);
        }
    }
}

// ---------------- FP16 tensor-core GEMM primitives --------------------------
__device__ __forceinline__ void mma_fp16(float& c0, float& c1, float& c2, float& c3,
                                         uint32_t a0, uint32_t a1, uint32_t a2, uint32_t a3,
                                         uint32_t b0, uint32_t b1) {
    asm volatile(
        "mma.sync.aligned.m16n8k16.row.col.f32.f16.f16.f32 "
        "{%0,%1,%2,%3},{%4,%5,%6,%7},{%8,%9},{%0,%1,%2,%3};"
        : "+f"(c0), "+f"(c1), "+f"(c2), "+f"(c3)
        : "r"(a0), "r"(a1), "r"(a2), "r"(a3), "r"(b0), "r"(b1));
}

#define LDSM_X4(r0, r1, r2, r3, addr)                                        \
    asm volatile("ldmatrix.sync.aligned.m8n8.x4.shared.b16 {%0,%1,%2,%3}, [%4];" \
                 : "=r"(r0), "=r"(r1), "=r"(r2), "=r"(r3) : "r"(addr))
#define LDSM_X4_T(r0, r1, r2, r3, addr)                                      \
    asm volatile("ldmatrix.sync.aligned.m8n8.x4.trans.shared.b16 {%0,%1,%2,%3}, [%4];" \
                 : "=r"(r0), "=r"(r1), "=r"(r2), "=r"(r3) : "r"(addr))

__device__ __forceinline__ uint2 pack_half4(float4 v) {
    __half2 h01 = __floats2half2_rn(v.x, v.y);
    __half2 h23 = __floats2half2_rn(v.z, v.w);
    uint2 p;
    p.x = *(uint32_t*)&h01;
    p.y = *(uint32_t*)&h23;
    return p;
}

// ---- N=64 tile (8 warps, warp m16n32) — used for gemm_in and s projection --
__device__ __forceinline__ void gemm_tile_fp16(
    const float* __restrict__ A, const float* __restrict__ W,
    const float* __restrict__ bias, float* __restrict__ C, __half* __restrict__ Ch,
    int n, int K, int Mw, int Mc, int row0, int colW, int colC) {

    __shared__ __align__(16) __half As[64][72];
    __shared__ __align__(16) __half Bs[64][72];

    int tid  = threadIdx.x;
    int lane = tid & 31;
    int wid  = tid >> 5;
    int wm   = wid & 3;
    int wn   = wid >> 2;
    int g    = lane >> 2;
    int tg   = lane & 3;
    int lrow = (lane < 16) ? lane : lane - 16;
    int lcol = (lane < 16) ? 0 : 8;

    float acc[4][4] = {};

    for (int kt = 0; kt < K; kt += 64) {
        #pragma unroll
        for (int i = 0; i < 4; i++) {
            int idx = i * 256 + tid;
            int r = idx >> 4, c4 = idx & 15;
            float4 av = make_float4(0.f, 0.f, 0.f, 0.f);
            int gr = row0 + r;
            if (gr < n) av = *(const float4*)(A + (size_t)gr * K + kt + c4 * 4);
            *(uint2*)&As[r][c4 * 4] = pack_half4(av);
        }
        #pragma unroll
        for (int i = 0; i < 4; i++) {
            int idx = i * 256 + tid;
            int r = idx >> 4, c4 = idx & 15;
            float4 bv = *(const float4*)(W + (size_t)(kt + r) * Mw + colW + c4 * 4);
            *(uint2*)&Bs[r][c4 * 4] = pack_half4(bv);
        }
        __syncthreads();

        #pragma unroll
        for (int ks = 0; ks < 4; ks++) {
            int k0 = ks * 16;
            uint32_t a0, a1, a2, a3;
            uint32_t aaddr = (uint32_t)__cvta_generic_to_shared(
                &As[wm * 16 + lrow][k0 + lcol]);
            LDSM_X4(a0, a1, a2, a3, aaddr);

            uint32_t b00, b01, b10, b11;
            uint32_t baddr0 = (uint32_t)__cvta_generic_to_shared(
                &Bs[k0 + lrow][wn * 32 + lcol]);
            LDSM_X4_T(b00, b01, b10, b11, baddr0);
            uint32_t b20, b21, b30, b31;
            uint32_t baddr1 = (uint32_t)__cvta_generic_to_shared(
                &Bs[k0 + lrow][wn * 32 + 16 + lcol]);
            LDSM_X4_T(b20, b21, b30, b31, baddr1);

            mma_fp16(acc[0][0], acc[0][1], acc[0][2], acc[0][3],
                     a0, a1, a2, a3, b00, b01);
            mma_fp16(acc[1][0], acc[1][1], acc[1][2], acc[1][3],
                     a0, a1, a2, a3, b10, b11);
            mma_fp16(acc[2][0], acc[2][1], acc[2][2], acc[2][3],
                     a0, a1, a2, a3, b20, b21);
            mma_fp16(acc[3][0], acc[3][1], acc[3][2], acc[3][3],
                     a0, a1, a2, a3, b30, b31);
        }
        __syncthreads();
    }

    #pragma unroll
    for (int j = 0; j < 4; j++) {
        int n0 = wn * 32 + j * 8;
        int cw = colW + n0 + tg * 2;
        int cc = colC + n0 + tg * 2;
        float b0 = bias[cw], b1 = bias[cw + 1];
        int r0 = row0 + wm * 16 + g;
        int r1 = r0 + 8;
        if (Ch) {
            if (r0 < n)
                *(__half2*)(Ch + (size_t)r0 * Mc + cc) =
                    __floats2half2_rn(acc[j][0] + b0, acc[j][1] + b1);
            if (r1 < n)
                *(__half2*)(Ch + (size_t)r1 * Mc + cc) =
                    __floats2half2_rn(acc[j][2] + b0, acc[j][3] + b1);
        } else {
            if (r0 < n)
                *(float2*)(C + (size_t)r0 * Mc + cc) =
                    make_float2(acc[j][0] + b0, acc[j][1] + b1);
            if (r1 < n)
                *(float2*)(C + (size_t)r1 * Mc + cc) =
                    make_float2(acc[j][2] + b0, acc[j][3] + b1);
        }
    }
}

// ---- N=128 tile (8 warps, warp m16n64) — used for q/k/v projections --------
__device__ __forceinline__ void gemm_tile_fp16_n128(
    const float* __restrict__ A, const float* __restrict__ W,
    const float* __restrict__ bias, float* __restrict__ C, __half* __restrict__ Ch,
    int n, int Mw, int Mc, int row0, int colW, int colC) {

    __shared__ __align__(16) __half As[64][72];
    __shared__ __align__(16) __half Bs[64][136];

    int tid  = threadIdx.x;
    int lane = tid & 31;
    int wid  = tid >> 5;
    int wm   = wid & 3;
    int wn   = wid >> 2;
    int g    = lane >> 2;
    int tg   = lane & 3;
    int lrow = (lane < 16) ? lane : lane - 16;
    int lcol = (lane < 16) ? 0 : 8;

    float acc[8][4] = {};

    #pragma unroll
    for (int i = 0; i < 4; i++) {
        int idx = i * 256 + tid;
        int r = idx >> 4, c4 = idx & 15;
        float4 av = make_float4(0.f, 0.f, 0.f, 0.f);
        int gr = row0 + r;
        if (gr < n) av = *(const float4*)(A + (size_t)gr * HD + c4 * 4);
        *(uint2*)&As[r][c4 * 4] = pack_half4(av);
    }
    #pragma unroll
    for (int i = 0; i < 8; i++) {
        int idx = i * 256 + tid;
        int r = idx >> 5, c4 = idx & 31;
        float4 bv = *(const float4*)(W + (size_t)r * Mw + colW + c4 * 4);
        *(uint2*)&Bs[r][c4 * 4] = pack_half4(bv);
    }
    __syncthreads();

    #pragma unroll
    for (int ks = 0; ks < 4; ks++) {
        int k0 = ks * 16;
        uint32_t a0, a1, a2, a3;
        uint32_t aaddr = (uint32_t)__cvta_generic_to_shared(
            &As[wm * 16 + lrow][k0 + lcol]);
        LDSM_X4(a0, a1, a2, a3, aaddr);

        uint32_t b[16];
        #pragma unroll
        for (int jj = 0; jj < 4; jj++) {
            uint32_t baddr = (uint32_t)__cvta_generic_to_shared(
                &Bs[k0 + lrow][wn * 64 + jj * 16 + lcol]);
            LDSM_X4_T(b[jj * 4], b[jj * 4 + 1], b[jj * 4 + 2], b[jj * 4 + 3], baddr);
        }
        #pragma unroll
        for (int jf = 0; jf < 8; jf++) {
            mma_fp16(acc[jf][0], acc[jf][1], acc[jf][2], acc[jf][3],
                     a0, a1, a2, a3, b[jf * 2], b[jf * 2 + 1]);
        }
    }

    #pragma unroll
    for (int j = 0; j < 8; j++) {
        int n0 = wn * 64 + j * 8;
        int cw = colW + n0 + tg * 2;
        int cc = colC + n0 + tg * 2;
        float b0 = bias[cw], b1 = bias[cw + 1];
        int r0 = row0 + wm * 16 + g;
        int r1 = r0 + 8;
        if (Ch) {
            if (r0 < n)
                *(__half2*)(Ch + (size_t)r0 * Mc + cc) =
                    __floats2half2_rn(acc[j][0] + b0, acc[j][1] + b1);
            if (r1 < n)
                *(__half2*)(Ch + (size_t)r1 * Mc + cc) =
                    __floats2half2_rn(acc[j][2] + b0, acc[j][3] + b1);
        } else {
            if (r0 < n)
                *(float2*)(C + (size_t)r0 * Mc + cc) =
                    make_float2(acc[j][0] + b0, acc[j][1] + b1);
            if (r1 < n)
                *(float2*)(C + (size_t)r1 * Mc + cc) =
                    make_float2(acc[j][2] + b0, acc[j][3] + b1);
        }
    }
}

__global__ __launch_bounds__(256) void k_gemm_in(const float* __restrict__ x,
                                                 const float* __restrict__ W,
                                                 const float* __restrict__ bias) {
    gemm_tile_fp16(x, W, bias, g_h0, nullptr, NN, IND, HD, HD, blockIdx.x * 64, 0, 0);
}

// fused q/k/v/s: grid.y = 7 (0-1 q, 2-3 k, 4-5 v [N=128 tiles], 6 s [N=64])
__global__ __launch_bounds__(256) void k_gemm_qkvs(int a_sel,
        const float* __restrict__ Wq, const float* __restrict__ bq,
        const float* __restrict__ Wk, const float* __restrict__ bk,
        const float* __restrict__ Wv, const float* __restrict__ bv,
        const float* __restrict__ Ws, const float* __restrict__ bs) {
    const float* A = buf_sel(a_sel);
    int ct = blockIdx.y;
    if (ct == 6) {
        gemm_tile_fp16(A, Ws, bs, g_s, nullptr, NN, HD, HD, HD,
                       blockIdx.x * 64, 0, 0);
        return;
    }
    const float* W; const float* bias; float* C; __half* Ch; int col;
    if (ct < 2)       { W = Wq; bias = bq; C = g_q; Ch = nullptr; col = ct * 128; }
    else if (ct < 4)  { W = Wk; bias = bk; C = nullptr; Ch = g_kh; col = (ct - 2) * 128; }
    else              { W = Wv; bias = bv; C = nullptr; Ch = g_vh; col = (ct - 4) * 128; }
    gemm_tile_fp16_n128(A, W, bias, C, Ch, NN, QKVD, QKVD,
                        blockIdx.x * 64, col, col);
}

// ---------------- attention core: dual-accumulator online softmax -----------
// one warp per node; lane = head*8 + t; lane owns 8 contiguous fp16 columns.
// Even/odd edges feed two independent (m, denom, acc) states, merged at end.
// ATT_BODY computes acc[8] (head-mean pre-multiplied by inv denom then
// reduced over heads); caller handles the epilogue.
#define ATT_STEP(KC, VC, M, DEN, ACC)                                        \
    {                                                                        \
        const __half2* kh_ = (const __half2*)&(KC);                          \
        float2 kA = __half22float2(kh_[0]);                                  \
        float2 kB = __half22float2(kh_[1]);                                  \
        float2 kC = __half22float2(kh_[2]);                                  \
        float2 kD = __half22float2(kh_[3]);                                  \
        float d_ = qa.x * kA.x + qa.y * kA.y + qa.z * kB.x + qa.w * kB.y     \
                 + qb.x * kC.x + qb.y * kC.y + qb.z * kD.x + qb.w * kD.y;    \
        d_ += __shfl_xor_sync(0xffffffffu, d_, 1);                           \
        d_ += __shfl_xor_sync(0xffffffffu, d_, 2);                           \
        d_ += __shfl_xor_sync(0xffffffffu, d_, 4);                           \
        d_ *= 0.125f;                                                        \
        float nm_   = fmaxf(M, d_);                                          \
        float corr_ = __expf(M - nm_);                                       \
        float ex_   = __expf(d_ - nm_);                                      \
        M = nm_;                                                             \
        DEN = DEN * corr_ + ex_;                                             \
        const __half2* vh_ = (const __half2*)&(VC);                          \
        float2 vA = __half22float2(vh_[0]);                                  \
        float2 vB = __half22float2(vh_[1]);                                  \
        float2 vC = __half22float2(vh_[2]);                                  \
        float2 vD = __half22float2(vh_[3]);                                  \
        ACC[0] = ACC[0] * corr_ + ex_ * vA.x;                                \
        ACC[1] = ACC[1] * corr_ + ex_ * vA.y;                                \
        ACC[2] = ACC[2] * corr_ + ex_ * vB.x;                                \
        ACC[3] = ACC[3] * corr_ + ex_ * vB.y;                                \
        ACC[4] = ACC[4] * corr_ + ex_ * vC.x;                                \
        ACC[5] = ACC[5] * corr_ + ex_ * vC.y;                                \
        ACC[6] = ACC[6] * corr_ + ex_ * vD.x;                                \
        ACC[7] = ACC[7] * corr_ + ex_ * vD.y;                                \
    }

__device__ __forceinline__ void attn_core(int node, int col,
                                          float4 qa, float4 qb,
                                          float (&acc)[8]) {
    int beg = g_rowptr[node], end = g_rowptr[node + 1];

    float m0 = -1e30f, den0 = 0.f;
    float m1 = -1e30f, den1 = 0.f;
    float a0[8] = {0.f, 0.f, 0.f, 0.f, 0.f, 0.f, 0.f, 0.f};
    float a1[8] = {0.f, 0.f, 0.f, 0.f, 0.f, 0.f, 0.f, 0.f};

    uint4 k0w, v0w, k1w, v1w;
    if (beg < end) {
        int s = g_srcs[beg];
        k0w = *(const uint4*)(g_kh + (size_t)s * QKVD + col);
        v0w = *(const uint4*)(g_vh + (size_t)s * QKVD + col);
    }
    if (beg + 1 < end) {
        int s = g_srcs[beg + 1];
        k1w = *(const uint4*)(g_kh + (size_t)s * QKVD + col);
        v1w = *(const uint4*)(g_vh + (size_t)s * QKVD + col);
    }

    for (int p = beg; p < end; p += 2) {
        uint4 kc0 = k0w, vc0 = v0w;
        if (p + 2 < end) {
            int s = g_srcs[p + 2];
            k0w = *(const uint4*)(g_kh + (size_t)s * QKVD + col);
            v0w = *(const uint4*)(g_vh + (size_t)s * QKVD + col);
        }
        uint4 kc1 = k1w, vc1 = v1w;
        bool has1 = (p + 1 < end);
        if (p + 3 < end) {
            int s = g_srcs[p + 3];
            k1w = *(const uint4*)(g_kh + (size_t)s * QKVD + col);
            v1w = *(const uint4*)(g_vh + (size_t)s * QKVD + col);
        }
        ATT_STEP(kc0, vc0, m0, den0, a0);
        if (has1) ATT_STEP(kc1, vc1, m1, den1, a1);
    }

    // merge the two softmax states
    float mm = fmaxf(m0, m1);
    float c0 = __expf(m0 - mm);
    float c1 = __expf(m1 - mm);
    float denom = den0 * c0 + den1 * c1;
    float inv = denom > 0.f ? 1.f / denom : 0.f;

    #pragma unroll
    for (int j = 0; j < 8; j++) {
        float o = (a0[j] * c0 + a1[j] * c1) * inv;
        o += __shfl_xor_sync(0xffffffffu, o, 8);
        o += __shfl_xor_sync(0xffffffffu, o, 16);
        acc[j] = o;
    }
}

// layers 0..NL-2: write h to buffer with ReLU
__global__ void k_attn(int out_sel) {
    int node = (blockIdx.x * blockDim.x + threadIdx.x) >> 5;
    if (node >= NN) return;
    int lane = threadIdx.x & 31;
    int h = lane >> 3, t = lane & 7;
    int col = h * 64 + t * 8;

    const float4* qp = (const float4*)(g_q + (size_t)node * QKVD + col);
    float4 qa = qp[0], qb = qp[1];

    float acc[8];
    attn_core(node, col, qa, qb, acc);

    if (h == 0) {
        const float* sp = g_s + (size_t)node * HD + t * 8;
        float* op = buf_sel(out_sel) + (size_t)node * HD + t * 8;
        #pragma unroll
        for (int j = 0; j < 8; j++) {
            float val = 0.25f * acc[j] + sp[j];   // head mean + skip
            op[j] = fmaxf(val, 0.f);              // ReLU
        }
    }
}

// last layer: fused ReLU + global_add_pool (separate kernel -> lean regs
// for the non-pool layers)
__global__ void k_attn_pool(const void* __restrict__ batch,
                            float* __restrict__ out) {
    int node = (blockIdx.x * blockDim.x + threadIdx.x) >> 5;
    if (node >= NN) return;
    int lane = threadIdx.x & 31;
    int h = lane >> 3, t = lane & 7;
    int col = h * 64 + t * 8;

    const float4* qp = (const float4*)(g_q + (size_t)node * QKVD + col);
    float4 qa = qp[0], qb = qp[1];

    float acc[8];
    attn_core(node, col, qa, qb, acc);

    if (h == 0) {
        const float* sp = g_s + (size_t)node * HD + t * 8;
        int gidx = g_use32 ? ((const int*)batch)[node]
                           : (int)((const long long*)batch)[node];
        gidx = gidx < 0 ? 0 : (gidx >= NG ? NG - 1 : gidx);
        float* op = out + (size_t)gidx * HD + t * 8;
        #pragma unroll
        for (int j = 0; j < 8; j++) {
            float val = fmaxf(0.25f * acc[j] + sp[j], 0.f);
            atomicAdd(&op[j], val);
        }
    }
}

// ---------------- out zero ---------------------------------------------------
__global__ void k_pool_zero(float* out) {
    int i = blockIdx.x * blockDim.x + threadIdx.x;
    if (i < NG * HD) out[i] = 0.f;
}

// ---------------- host ------------------------------------------------------
extern "C" void kernel_launch(void* const* d_in, const int* in_sizes, int n_in,
                              void* d_out, int out_size) {
    (void)in_sizes; (void)n_in; (void)out_size;
    const float* x     = (const float*)d_in[0];
    const void*  ei    = d_in[1];
    const void*  batch = d_in[2];
    const float* lin_W = (const float*)d_in[3];
    const float* lin_b = (const float*)d_in[4];
    const float* Wq = (const float*)d_in[5];
    const float* bq = (const float*)d_in[6];
    const float* Wk = (const float*)d_in[7];
    const float* bk = (const float*)d_in[8];
    const float* Wv = (const float*)d_in[9];
    const float* bv = (const float*)d_in[10];
    const float* Ws = (const float*)d_in[11];
    const float* bs = (const float*)d_in[12];

    // side stream for CSR build + output zeroing (fork/join, capture-legal)
    cudaStream_t s2;
    cudaStreamCreateWithFlags(&s2, cudaStreamNonBlocking);
    cudaEvent_t eFork, eJoin;
    cudaEventCreateWithFlags(&eFork, cudaEventDisableTiming);
    cudaEventCreateWithFlags(&eJoin, cudaEventDisableTiming);

    cudaEventRecord(eFork, 0);
    cudaStreamWaitEvent(s2, eFork, 0);

    k_pool_zero<<<(NG * HD + 255) / 256, 256, 0, s2>>>((float*)d_out);
    k_detect<<<1, 32, 0, s2>>>(ei);
    k_zero_cnt<<<(NN + 255) / 256, 256, 0, s2>>>();
    k_count<<<(EE / 4 + 255) / 256, 256, 0, s2>>>(ei);
    k_scan1<<<NB, 256, 0, s2>>>();
    k_scan2<<<1, 128, 0, s2>>>();
    k_scan3<<<NB, 256, 0, s2>>>();
    k_scatter<<<(EE / 4 + 255) / 256, 256, 0, s2>>>(ei);
    cudaEventRecord(eJoin, s2);

    const int RT = (NN + 63) / 64;  // 313 row tiles

    k_gemm_in<<<dim3(RT, 1), 256>>>(x, lin_W, lin_b);

    int hin = 0, hou = 1;
    for (int l = 0; l < NL; l++) {
        k_gemm_qkvs<<<dim3(RT, 7), 256>>>(hin,
            Wq + (size_t)l * HD * QKVD, bq + (size_t)l * QKVD,
            Wk + (size_t)l * HD * QKVD, bk + (size_t)l * QKVD,
            Wv + (size_t)l * HD * QKVD, bv + (size_t)l * QKVD,
            Ws + (size_t)l * HD * HD,   bs + (size_t)l * HD);
        if (l == 0) cudaStreamWaitEvent(0, eJoin, 0);   // CSR + zeroed out ready
        if (l == NL - 1)
            k_attn_pool<<<(NN * 32 + 255) / 256, 256>>>(batch, (float*)d_out);
        else
            k_attn<<<(NN * 32 + 255) / 256, 256>>>(hou);
        int tmp = hin; hin = hou; hou = tmp;
    }
}

// round 16
// speedup vs baseline: 1.2022x; 1.2022x over previous
#include <cuda_runtime.h>
#include <cuda_fp16.h>
#include <cstdint>

#define NN   20000
#define EE   320000
#define IND  128
#define HD   64
#define NH   4
#define QKVD 256   // NH * HD
#define NL   3
#define NG   128
#define NB   79    // scan blocks: ceil(NN/256)

// ---------------- scratch (device globals) ----------------------------------
__device__ float  g_h0[NN * HD];
__device__ float  g_h1[NN * HD];
__device__ float  g_q[NN * QKVD];
__device__ __half g_kh[NN * QKVD];
__device__ __half g_vh[NN * QKVD];
__device__ float  g_s[NN * HD];
__device__ int    g_cnt[NN];
__device__ int    g_rowptr[NN + 1];
__device__ int    g_cursor[NN];
__device__ int    g_srcs[EE];
__device__ int    g_bsum[128];
__device__ int    g_boff[128];
__device__ int    g_use32;   // 1 => edge_index/batch are int32, 0 => int64

__device__ __forceinline__ float* buf_sel(int s) {
    return s == 0 ? g_h0 : g_h1;
}

__device__ __forceinline__ int clampN(int i) {
    return i < 0 ? 0 : (i >= NN ? NN - 1 : i);
}

// ---------------- dtype detection -------------------------------------------
__global__ void k_detect(const void* __restrict__ ei) {
    const long long* p = (const long long*)ei;
    int t = threadIdx.x;           // 32 threads
    long long v = p[t];
    unsigned bad = __ballot_sync(0xffffffffu, v < 0 || v >= (long long)NN);
    if (t == 0) g_use32 = (bad != 0u) ? 1 : 0;
}

// ---------------- CSR build (counting sort by dst) --------------------------
__global__ void k_zero_cnt() {
    int i = blockIdx.x * blockDim.x + threadIdx.x;
    if (i < NN) g_cnt[i] = 0;
}

// 4 edges per thread, vectorized index loads
__global__ void k_count(const void* __restrict__ ei) {
    int e4 = blockIdx.x * blockDim.x + threadIdx.x;
    if (e4 < EE / 4) {
        int d[4];
        if (g_use32) {
            int4 dd = *((const int4*)ei + (EE + 4 * e4) / 4);
            d[0] = dd.x; d[1] = dd.y; d[2] = dd.z; d[3] = dd.w;
        } else {
            longlong2 a = *((const longlong2*)ei + (EE + 4 * e4) / 2);
            longlong2 b = *((const longlong2*)ei + (EE + 4 * e4) / 2 + 1);
            d[0] = (int)a.x; d[1] = (int)a.y; d[2] = (int)b.x; d[3] = (int)b.y;
        }
        #pragma unroll
        for (int j = 0; j < 4; j++) atomicAdd(&g_cnt[clampN(d[j])], 1);
    }
}

__global__ void k_scan1() {
    __shared__ int ws[8];
    int t = threadIdx.x, lane = t & 31, wid = t >> 5;
    int i = blockIdx.x * 256 + t;
    int v = (i < NN) ? g_cnt[i] : 0;
    int s = v;
    #pragma unroll
    for (int d = 16; d > 0; d >>= 1) s += __shfl_xor_sync(0xffffffffu, s, d);
    if (lane == 0) ws[wid] = s;
    __syncthreads();
    if (t < 8) {
        int x = ws[t];
        #pragma unroll
        for (int d = 4; d > 0; d >>= 1) x += __shfl_xor_sync(0xffu, x, d);
        if (t == 0) g_bsum[blockIdx.x] = x;
    }
}

__global__ void k_scan2() {
    __shared__ int wsum[4];
    int t = threadIdx.x, lane = t & 31, wid = t >> 5;
    int v = (t < NB) ? g_bsum[t] : 0;
    int incl = v;
    #pragma unroll
    for (int d = 1; d < 32; d <<= 1) {
        int nb = __shfl_up_sync(0xffffffffu, incl, d);
        if (lane >= d) incl += nb;
    }
    if (lane == 31) wsum[wid] = incl;
    __syncthreads();
    int off = 0;
    for (int w = 0; w < wid; w++) off += wsum[w];
    if (t < NB) g_boff[t] = off + incl - v;
}

__global__ void k_scan3() {
    __shared__ int wincl[8];
    int t = threadIdx.x, lane = t & 31, wid = t >> 5;
    int i = blockIdx.x * 256 + t;
    int v = (i < NN) ? g_cnt[i] : 0;
    int incl = v;
    #pragma unroll
    for (int d = 1; d < 32; d <<= 1) {
        int nb = __shfl_up_sync(0xffffffffu, incl, d);
        if (lane >= d) incl += nb;
    }
    if (lane == 31) wincl[wid] = incl;
    __syncthreads();
    int woff = 0;
    for (int w = 0; w < wid; w++) woff += wincl[w];
    int excl = g_boff[blockIdx.x] + woff + incl - v;
    if (i < NN) {
        g_cursor[i] = excl;
        g_rowptr[i + 1] = excl + v;
        if (i == 0) g_rowptr[0] = 0;
    }
}

// 4 edges per thread, vectorized index loads
__global__ void k_scatter(const void* __restrict__ ei) {
    int e4 = blockIdx.x * blockDim.x + threadIdx.x;
    if (e4 < EE / 4) {
        int d[4], s[4];
        if (g_use32) {
            int4 dd = *((const int4*)ei + (EE + 4 * e4) / 4);
            int4 ss = *((const int4*)ei + (4 * e4) / 4);
            d[0] = dd.x; d[1] = dd.y; d[2] = dd.z; d[3] = dd.w;
            s[0] = ss.x; s[1] = ss.y; s[2] = ss.z; s[3] = ss.w;
        } else {
            longlong2 a = *((const longlong2*)ei + (EE + 4 * e4) / 2);
            longlong2 b = *((const longlong2*)ei + (EE + 4 * e4) / 2 + 1);
            longlong2 c = *((const longlong2*)ei + (4 * e4) / 2);
            longlong2 e = *((const longlong2*)ei + (4 * e4) / 2 + 1);
            d[0] = (int)a.x; d[1] = (int)a.y; d[2] = (int)b.x; d[3] = (int)b.y;
            s[0] = (int)c.x; s[1] = (int)c.y; s[2] = (int)e.x; s[3] = (int)e.y;
        }
        #pragma unroll
        for (int j = 0; j < 4; j++) {
            int pos = atomicAdd(&g_cursor[clampN(d[j])], 1);
            g_srcs[pos] = clampN(s[j]);
        }
    }
}

// ---------------- FP16 tensor-core GEMM primitives --------------------------
__device__ __forceinline__ void mma_fp16(float& c0, float& c1, float& c2, float& c3,
                                         uint32_t a0, uint32_t a1, uint32_t a2, uint32_t a3,
                                         uint32_t b0, uint32_t b1) {
    asm volatile(
        "mma.sync.aligned.m16n8k16.row.col.f32.f16.f16.f32 "
        "{%0,%1,%2,%3},{%4,%5,%6,%7},{%8,%9},{%0,%1,%2,%3};"
        : "+f"(c0), "+f"(c1), "+f"(c2), "+f"(c3)
        : "r"(a0), "r"(a1), "r"(a2), "r"(a3), "r"(b0), "r"(b1));
}

#define LDSM_X4(r0, r1, r2, r3, addr)                                        \
    asm volatile("ldmatrix.sync.aligned.m8n8.x4.shared.b16 {%0,%1,%2,%3}, [%4];" \
                 : "=r"(r0), "=r"(r1), "=r"(r2), "=r"(r3) : "r"(addr))
#define LDSM_X4_T(r0, r1, r2, r3, addr)                                      \
    asm volatile("ldmatrix.sync.aligned.m8n8.x4.trans.shared.b16 {%0,%1,%2,%3}, [%4];" \
                 : "=r"(r0), "=r"(r1), "=r"(r2), "=r"(r3) : "r"(addr))

__device__ __forceinline__ uint2 pack_half4(float4 v) {
    __half2 h01 = __floats2half2_rn(v.x, v.y);
    __half2 h23 = __floats2half2_rn(v.z, v.w);
    uint2 p;
    p.x = *(uint32_t*)&h01;
    p.y = *(uint32_t*)&h23;
    return p;
}

// ---- N=64 tile (8 warps, warp m16n32) — used for gemm_in and s projection --
__device__ __forceinline__ void gemm_tile_fp16(
    const float* __restrict__ A, const float* __restrict__ W,
    const float* __restrict__ bias, float* __restrict__ C, __half* __restrict__ Ch,
    int n, int K, int Mw, int Mc, int row0, int colW, int colC) {

    __shared__ __align__(16) __half As[64][72];
    __shared__ __align__(16) __half Bs[64][72];

    int tid  = threadIdx.x;
    int lane = tid & 31;
    int wid  = tid >> 5;
    int wm   = wid & 3;
    int wn   = wid >> 2;
    int g    = lane >> 2;
    int tg   = lane & 3;
    int lrow = (lane < 16) ? lane : lane - 16;
    int lcol = (lane < 16) ? 0 : 8;

    float acc[4][4] = {};

    for (int kt = 0; kt < K; kt += 64) {
        #pragma unroll
        for (int i = 0; i < 4; i++) {
            int idx = i * 256 + tid;
            int r = idx >> 4, c4 = idx & 15;
            float4 av = make_float4(0.f, 0.f, 0.f, 0.f);
            int gr = row0 + r;
            if (gr < n) av = *(const float4*)(A + (size_t)gr * K + kt + c4 * 4);
            *(uint2*)&As[r][c4 * 4] = pack_half4(av);
        }
        #pragma unroll
        for (int i = 0; i < 4; i++) {
            int idx = i * 256 + tid;
            int r = idx >> 4, c4 = idx & 15;
            float4 bv = *(const float4*)(W + (size_t)(kt + r) * Mw + colW + c4 * 4);
            *(uint2*)&Bs[r][c4 * 4] = pack_half4(bv);
        }
        __syncthreads();

        #pragma unroll
        for (int ks = 0; ks < 4; ks++) {
            int k0 = ks * 16;
            uint32_t a0, a1, a2, a3;
            uint32_t aaddr = (uint32_t)__cvta_generic_to_shared(
                &As[wm * 16 + lrow][k0 + lcol]);
            LDSM_X4(a0, a1, a2, a3, aaddr);

            uint32_t b00, b01, b10, b11;
            uint32_t baddr0 = (uint32_t)__cvta_generic_to_shared(
                &Bs[k0 + lrow][wn * 32 + lcol]);
            LDSM_X4_T(b00, b01, b10, b11, baddr0);
            uint32_t b20, b21, b30, b31;
            uint32_t baddr1 = (uint32_t)__cvta_generic_to_shared(
                &Bs[k0 + lrow][wn * 32 + 16 + lcol]);
            LDSM_X4_T(b20, b21, b30, b31, baddr1);

            mma_fp16(acc[0][0], acc[0][1], acc[0][2], acc[0][3],
                     a0, a1, a2, a3, b00, b01);
            mma_fp16(acc[1][0], acc[1][1], acc[1][2], acc[1][3],
                     a0, a1, a2, a3, b10, b11);
            mma_fp16(acc[2][0], acc[2][1], acc[2][2], acc[2][3],
                     a0, a1, a2, a3, b20, b21);
            mma_fp16(acc[3][0], acc[3][1], acc[3][2], acc[3][3],
                     a0, a1, a2, a3, b30, b31);
        }
        __syncthreads();
    }

    #pragma unroll
    for (int j = 0; j < 4; j++) {
        int n0 = wn * 32 + j * 8;
        int cw = colW + n0 + tg * 2;
        int cc = colC + n0 + tg * 2;
        float b0 = bias[cw], b1 = bias[cw + 1];
        int r0 = row0 + wm * 16 + g;
        int r1 = r0 + 8;
        if (Ch) {
            if (r0 < n)
                *(__half2*)(Ch + (size_t)r0 * Mc + cc) =
                    __floats2half2_rn(acc[j][0] + b0, acc[j][1] + b1);
            if (r1 < n)
                *(__half2*)(Ch + (size_t)r1 * Mc + cc) =
                    __floats2half2_rn(acc[j][2] + b0, acc[j][3] + b1);
        } else {
            if (r0 < n)
                *(float2*)(C + (size_t)r0 * Mc + cc) =
                    make_float2(acc[j][0] + b0, acc[j][1] + b1);
            if (r1 < n)
                *(float2*)(C + (size_t)r1 * Mc + cc) =
                    make_float2(acc[j][2] + b0, acc[j][3] + b1);
        }
    }
}

// ---- N=128 tile (8 warps, warp m16n64) — used for q/k/v projections --------
__device__ __forceinline__ void gemm_tile_fp16_n128(
    const float* __restrict__ A, const float* __restrict__ W,
    const float* __restrict__ bias, float* __restrict__ C, __half* __restrict__ Ch,
    int n, int Mw, int Mc, int row0, int colW, int colC) {

    __shared__ __align__(16) __half As[64][72];
    __shared__ __align__(16) __half Bs[64][136];

    int tid  = threadIdx.x;
    int lane = tid & 31;
    int wid  = tid >> 5;
    int wm   = wid & 3;
    int wn   = wid >> 2;
    int g    = lane >> 2;
    int tg   = lane & 3;
    int lrow = (lane < 16) ? lane : lane - 16;
    int lcol = (lane < 16) ? 0 : 8;

    float acc[8][4] = {};

    #pragma unroll
    for (int i = 0; i < 4; i++) {
        int idx = i * 256 + tid;
        int r = idx >> 4, c4 = idx & 15;
        float4 av = make_float4(0.f, 0.f, 0.f, 0.f);
        int gr = row0 + r;
        if (gr < n) av = *(const float4*)(A + (size_t)gr * HD + c4 * 4);
        *(uint2*)&As[r][c4 * 4] = pack_half4(av);
    }
    #pragma unroll
    for (int i = 0; i < 8; i++) {
        int idx = i * 256 + tid;
        int r = idx >> 5, c4 = idx & 31;
        float4 bv = *(const float4*)(W + (size_t)r * Mw + colW + c4 * 4);
        *(uint2*)&Bs[r][c4 * 4] = pack_half4(bv);
    }
    __syncthreads();

    #pragma unroll
    for (int ks = 0; ks < 4; ks++) {
        int k0 = ks * 16;
        uint32_t a0, a1, a2, a3;
        uint32_t aaddr = (uint32_t)__cvta_generic_to_shared(
            &As[wm * 16 + lrow][k0 + lcol]);
        LDSM_X4(a0, a1, a2, a3, aaddr);

        uint32_t b[16];
        #pragma unroll
        for (int jj = 0; jj < 4; jj++) {
            uint32_t baddr = (uint32_t)__cvta_generic_to_shared(
                &Bs[k0 + lrow][wn * 64 + jj * 16 + lcol]);
            LDSM_X4_T(b[jj * 4], b[jj * 4 + 1], b[jj * 4 + 2], b[jj * 4 + 3], baddr);
        }
        #pragma unroll
        for (int jf = 0; jf < 8; jf++) {
            mma_fp16(acc[jf][0], acc[jf][1], acc[jf][2], acc[jf][3],
                     a0, a1, a2, a3, b[jf * 2], b[jf * 2 + 1]);
        }
    }

    #pragma unroll
    for (int j = 0; j < 8; j++) {
        int n0 = wn * 64 + j * 8;
        int cw = colW + n0 + tg * 2;
        int cc = colC + n0 + tg * 2;
        float b0 = bias[cw], b1 = bias[cw + 1];
        int r0 = row0 + wm * 16 + g;
        int r1 = r0 + 8;
        if (Ch) {
            if (r0 < n)
                *(__half2*)(Ch + (size_t)r0 * Mc + cc) =
                    __floats2half2_rn(acc[j][0] + b0, acc[j][1] + b1);
            if (r1 < n)
                *(__half2*)(Ch + (size_t)r1 * Mc + cc) =
                    __floats2half2_rn(acc[j][2] + b0, acc[j][3] + b1);
        } else {
            if (r0 < n)
                *(float2*)(C + (size_t)r0 * Mc + cc) =
                    make_float2(acc[j][0] + b0, acc[j][1] + b1);
            if (r1 < n)
                *(float2*)(C + (size_t)r1 * Mc + cc) =
                    make_float2(acc[j][2] + b0, acc[j][3] + b1);
        }
    }
}

__global__ __launch_bounds__(256) void k_gemm_in(const float* __restrict__ x,
                                                 const float* __restrict__ W,
                                                 const float* __restrict__ bias) {
    gemm_tile_fp16(x, W, bias, g_h0, nullptr, NN, IND, HD, HD, blockIdx.x * 64, 0, 0);
}

// fused q/k/v/s: grid.y = 7 (0-1 q, 2-3 k, 4-5 v [N=128 tiles], 6 s [N=64])
__global__ __launch_bounds__(256) void k_gemm_qkvs(int a_sel,
        const float* __restrict__ Wq, const float* __restrict__ bq,
        const float* __restrict__ Wk, const float* __restrict__ bk,
        const float* __restrict__ Wv, const float* __restrict__ bv,
        const float* __restrict__ Ws, const float* __restrict__ bs) {
    const float* A = buf_sel(a_sel);
    int ct = blockIdx.y;
    if (ct == 6) {
        gemm_tile_fp16(A, Ws, bs, g_s, nullptr, NN, HD, HD, HD,
                       blockIdx.x * 64, 0, 0);
        return;
    }
    const float* W; const float* bias; float* C; __half* Ch; int col;
    if (ct < 2)       { W = Wq; bias = bq; C = g_q; Ch = nullptr; col = ct * 128; }
    else if (ct < 4)  { W = Wk; bias = bk; C = nullptr; Ch = g_kh; col = (ct - 2) * 128; }
    else              { W = Wv; bias = bv; C = nullptr; Ch = g_vh; col = (ct - 4) * 128; }
    gemm_tile_fp16_n128(A, W, bias, C, Ch, NN, QKVD, QKVD,
                        blockIdx.x * 64, col, col);
}

// ---------------- per-node attention: single-pass online softmax ------------
// one warp per node; lane = head*8 + t; lane owns 8 contiguous fp16 columns.
// (R14-validated lean form — do not add register state.)
__global__ void k_attn(int out_sel) {
    int node = (blockIdx.x * blockDim.x + threadIdx.x) >> 5;
    if (node >= NN) return;
    float* hout = buf_sel(out_sel);
    int lane = threadIdx.x & 31;
    int h = lane >> 3, t = lane & 7;
    int col = h * 64 + t * 8;

    const float4* qp = (const float4*)(g_q + (size_t)node * QKVD + col);
    float4 qa = qp[0], qb = qp[1];

    int beg = g_rowptr[node], end = g_rowptr[node + 1];

    float m = -1e30f, denom = 0.f;
    float acc[8] = {0.f, 0.f, 0.f, 0.f, 0.f, 0.f, 0.f, 0.f};

    uint4 kw, vw;
    if (beg < end) {
        int s0 = g_srcs[beg];
        kw = *(const uint4*)(g_kh + (size_t)s0 * QKVD + col);
        vw = *(const uint4*)(g_vh + (size_t)s0 * QKVD + col);
    }

    for (int p = beg; p < end; ++p) {
        uint4 kc = kw, vc = vw;
        if (p + 1 < end) {
            int s1 = g_srcs[p + 1];
            kw = *(const uint4*)(g_kh + (size_t)s1 * QKVD + col);
            vw = *(const uint4*)(g_vh + (size_t)s1 * QKVD + col);
        }

        const __half2* kh = (const __half2*)&kc;
        float2 k0 = __half22float2(kh[0]);
        float2 k1 = __half22float2(kh[1]);
        float2 k2 = __half22float2(kh[2]);
        float2 k3 = __half22float2(kh[3]);

        float d = qa.x * k0.x + qa.y * k0.y + qa.z * k1.x + qa.w * k1.y
                + qb.x * k2.x + qb.y * k2.y + qb.z * k3.x + qb.w * k3.y;
        d += __shfl_xor_sync(0xffffffffu, d, 1);
        d += __shfl_xor_sync(0xffffffffu, d, 2);
        d += __shfl_xor_sync(0xffffffffu, d, 4);
        d *= 0.125f;                       // 1/sqrt(64)

        float nm   = fmaxf(m, d);
        float corr = __expf(m - nm);
        float ex   = __expf(d - nm);
        m = nm;
        denom = denom * corr + ex;

        const __half2* vh = (const __half2*)&vc;
        float2 v0 = __half22float2(vh[0]);
        float2 v1 = __half22float2(vh[1]);
        float2 v2 = __half22float2(vh[2]);
        float2 v3 = __half22float2(vh[3]);
        acc[0] = acc[0] * corr + ex * v0.x;
        acc[1] = acc[1] * corr + ex * v0.y;
        acc[2] = acc[2] * corr + ex * v1.x;
        acc[3] = acc[3] * corr + ex * v1.y;
        acc[4] = acc[4] * corr + ex * v2.x;
        acc[5] = acc[5] * corr + ex * v2.y;
        acc[6] = acc[6] * corr + ex * v3.x;
        acc[7] = acc[7] * corr + ex * v3.y;
    }
    float inv = denom > 0.f ? 1.f / denom : 0.f;

    #pragma unroll
    for (int j = 0; j < 8; j++) {
        float o = acc[j] * inv;
        o += __shfl_xor_sync(0xffffffffu, o, 8);
        o += __shfl_xor_sync(0xffffffffu, o, 16);
        acc[j] = o;
    }

    if (h == 0) {
        const float* sp = g_s + (size_t)node * HD + t * 8;
        float* op = hout + (size_t)node * HD + t * 8;
        #pragma unroll
        for (int j = 0; j < 8; j++) {
            float val = 0.25f * acc[j] + sp[j];   // head mean + skip
            op[j] = fmaxf(val, 0.f);              // ReLU
        }
    }
}

// ---------------- global add pool -------------------------------------------
__global__ void k_pool_zero(float* out) {
    int i = blockIdx.x * blockDim.x + threadIdx.x;
    if (i < NG * HD) out[i] = 0.f;
}

// batch is sorted: each thread owns one column over 16 consecutive rows,
// accumulating locally and flushing on graph-index change (~1-2 atomics).
#define POOL_RPT 16
__global__ void k_pool(int in_sel, const void* __restrict__ batch,
                       float* out) {
    const float* hh = buf_sel(in_sel);
    int i = blockIdx.x * blockDim.x + threadIdx.x;
    int ngroups = (NN + POOL_RPT - 1) / POOL_RPT;   // 1250
    if (i >= ngroups * HD) return;
    int colc = i & 63;
    int row0 = (i >> 6) * POOL_RPT;
    int rend = row0 + POOL_RPT; if (rend > NN) rend = NN;

    int curg = -1;
    float sum = 0.f;
    for (int r = row0; r < rend; ++r) {
        int g = g_use32 ? ((const int*)batch)[r]
                        : (int)((const long long*)batch)[r];
        g = g < 0 ? 0 : (g >= NG ? NG - 1 : g);
        if (g != curg) {
            if (curg >= 0) atomicAdd(&out[curg * HD + colc], sum);
            curg = g; sum = 0.f;
        }
        sum += hh[(size_t)r * HD + colc];
    }
    if (curg >= 0) atomicAdd(&out[curg * HD + colc], sum);
}

// ---------------- host ------------------------------------------------------
extern "C" void kernel_launch(void* const* d_in, const int* in_sizes, int n_in,
                              void* d_out, int out_size) {
    (void)in_sizes; (void)n_in; (void)out_size;
    const float* x     = (const float*)d_in[0];
    const void*  ei    = d_in[1];
    const void*  batch = d_in[2];
    const float* lin_W = (const float*)d_in[3];
    const float* lin_b = (const float*)d_in[4];
    const float* Wq = (const float*)d_in[5];
    const float* bq = (const float*)d_in[6];
    const float* Wk = (const float*)d_in[7];
    const float* bk = (const float*)d_in[8];
    const float* Wv = (const float*)d_in[9];
    const float* bv = (const float*)d_in[10];
    const float* Ws = (const float*)d_in[11];
    const float* bs = (const float*)d_in[12];

    // side stream for CSR build + output zeroing (fork/join, capture-legal)
    cudaStream_t s2;
    cudaStreamCreateWithFlags(&s2, cudaStreamNonBlocking);
    cudaEvent_t eFork, eJoin;
    cudaEventCreateWithFlags(&eFork, cudaEventDisableTiming);
    cudaEventCreateWithFlags(&eJoin, cudaEventDisableTiming);

    cudaEventRecord(eFork, 0);
    cudaStreamWaitEvent(s2, eFork, 0);

    k_pool_zero<<<(NG * HD + 255) / 256, 256, 0, s2>>>((float*)d_out);
    k_detect<<<1, 32, 0, s2>>>(ei);
    k_zero_cnt<<<(NN + 255) / 256, 256, 0, s2>>>();
    k_count<<<(EE / 4 + 255) / 256, 256, 0, s2>>>(ei);
    k_scan1<<<NB, 256, 0, s2>>>();
    k_scan2<<<1, 128, 0, s2>>>();
    k_scan3<<<NB, 256, 0, s2>>>();
    k_scatter<<<(EE / 4 + 255) / 256, 256, 0, s2>>>(ei);
    cudaEventRecord(eJoin, s2);

    const int RT = (NN + 63) / 64;  // 313 row tiles

    k_gemm_in<<<dim3(RT, 1), 256>>>(x, lin_W, lin_b);

    int hin = 0, hou = 1;
    for (int l = 0; l < NL; l++) {
        k_gemm_qkvs<<<dim3(RT, 7), 256>>>(hin,
            Wq + (size_t)l * HD * QKVD, bq + (size_t)l * QKVD,
            Wk + (size_t)l * HD * QKVD, bk + (size_t)l * QKVD,
            Wv + (size_t)l * HD * QKVD, bv + (size_t)l * QKVD,
            Ws + (size_t)l * HD * HD,   bs + (size_t)l * HD);
        if (l == 0) cudaStreamWaitEvent(0, eJoin, 0);   // CSR + zeroed out ready
        k_attn<<<(NN * 32 + 255) / 256, 256>>>(hou);
        int tmp = hin; hin = hou; hou = tmp;
    }

    const int PG = ((NN + POOL_RPT - 1) / POOL_RPT) * HD;  // 80000 threads
    k_pool<<<(PG + 255) / 256, 256>>>(hin, batch, (float*)d_out);
}

// round 17
// speedup vs baseline: 1.2371x; 1.0291x over previous
#include <cuda_runtime.h>
#include <cuda_fp16.h>
#include <cstdint>

#define NN   20000
#define EE   320000
#define IND  128
#define HD   64
#define NH   4
#define QKVD 256   // NH * HD
#define NL   3
#define NG   128
#define NB   79    // scan blocks: ceil(NN/256)

// ---------------- scratch (device globals) ----------------------------------
__device__ __half g_h0[NN * HD];
__device__ __half g_h1[NN * HD];
__device__ __half g_qh[NN * QKVD];
__device__ __half g_kh[NN * QKVD];
__device__ __half g_vh[NN * QKVD];
__device__ float  g_s[NN * HD];
__device__ int    g_cnt[NN];
__device__ int    g_rowptr[NN + 1];
__device__ int    g_cursor[NN];
__device__ int    g_srcs[EE];
__device__ int    g_bsum[128];
__device__ int    g_boff[128];
__device__ int    g_use32;   // 1 => edge_index/batch are int32, 0 => int64

__device__ __forceinline__ __half* buf_sel(int s) {
    return s == 0 ? g_h0 : g_h1;
}

__device__ __forceinline__ int clampN(int i) {
    return i < 0 ? 0 : (i >= NN ? NN - 1 : i);
}

// ---------------- dtype detection -------------------------------------------
__global__ void k_detect(const void* __restrict__ ei) {
    const long long* p = (const long long*)ei;
    int t = threadIdx.x;           // 32 threads
    long long v = p[t];
    unsigned bad = __ballot_sync(0xffffffffu, v < 0 || v >= (long long)NN);
    if (t == 0) g_use32 = (bad != 0u) ? 1 : 0;
}

// ---------------- CSR build (counting sort by dst) --------------------------
__global__ void k_zero_cnt() {
    int i = blockIdx.x * blockDim.x + threadIdx.x;
    if (i < NN) g_cnt[i] = 0;
}

// 4 edges per thread, vectorized index loads
__global__ void k_count(const void* __restrict__ ei) {
    int e4 = blockIdx.x * blockDim.x + threadIdx.x;
    if (e4 < EE / 4) {
        int d[4];
        if (g_use32) {
            int4 dd = *((const int4*)ei + (EE + 4 * e4) / 4);
            d[0] = dd.x; d[1] = dd.y; d[2] = dd.z; d[3] = dd.w;
        } else {
            longlong2 a = *((const longlong2*)ei + (EE + 4 * e4) / 2);
            longlong2 b = *((const longlong2*)ei + (EE + 4 * e4) / 2 + 1);
            d[0] = (int)a.x; d[1] = (int)a.y; d[2] = (int)b.x; d[3] = (int)b.y;
        }
        #pragma unroll
        for (int j = 0; j < 4; j++) atomicAdd(&g_cnt[clampN(d[j])], 1);
    }
}

__global__ void k_scan1() {
    __shared__ int ws[8];
    int t = threadIdx.x, lane = t & 31, wid = t >> 5;
    int i = blockIdx.x * 256 + t;
    int v = (i < NN) ? g_cnt[i] : 0;
    int s = v;
    #pragma unroll
    for (int d = 16; d > 0; d >>= 1) s += __shfl_xor_sync(0xffffffffu, s, d);
    if (lane == 0) ws[wid] = s;
    __syncthreads();
    if (t < 8) {
        int x = ws[t];
        #pragma unroll
        for (int d = 4; d > 0; d >>= 1) x += __shfl_xor_sync(0xffu, x, d);
        if (t == 0) g_bsum[blockIdx.x] = x;
    }
}

__global__ void k_scan2() {
    __shared__ int wsum[4];
    int t = threadIdx.x, lane = t & 31, wid = t >> 5;
    int v = (t < NB) ? g_bsum[t] : 0;
    int incl = v;
    #pragma unroll
    for (int d = 1; d < 32; d <<= 1) {
        int nb = __shfl_up_sync(0xffffffffu, incl, d);
        if (lane >= d) incl += nb;
    }
    if (lane == 31) wsum[wid] = incl;
    __syncthreads();
    int off = 0;
    for (int w = 0; w < wid; w++) off += wsum[w];
    if (t < NB) g_boff[t] = off + incl - v;
}

__global__ void k_scan3() {
    __shared__ int wincl[8];
    int t = threadIdx.x, lane = t & 31, wid = t >> 5;
    int i = blockIdx.x * 256 + t;
    int v = (i < NN) ? g_cnt[i] : 0;
    int incl = v;
    #pragma unroll
    for (int d = 1; d < 32; d <<= 1) {
        int nb = __shfl_up_sync(0xffffffffu, incl, d);
        if (lane >= d) incl += nb;
    }
    if (lane == 31) wincl[wid] = incl;
    __syncthreads();
    int woff = 0;
    for (int w = 0; w < wid; w++) woff += wincl[w];
    int excl = g_boff[blockIdx.x] + woff + incl - v;
    if (i < NN) {
        g_cursor[i] = excl;
        g_rowptr[i + 1] = excl + v;
        if (i == 0) g_rowptr[0] = 0;
    }
}

// 4 edges per thread, vectorized index loads
__global__ void k_scatter(const void* __restrict__ ei) {
    int e4 = blockIdx.x * blockDim.x + threadIdx.x;
    if (e4 < EE / 4) {
        int d[4], s[4];
        if (g_use32) {
            int4 dd = *((const int4*)ei + (EE + 4 * e4) / 4);
            int4 ss = *((const int4*)ei + (4 * e4) / 4);
            d[0] = dd.x; d[1] = dd.y; d[2] = dd.z; d[3] = dd.w;
            s[0] = ss.x; s[1] = ss.y; s[2] = ss.z; s[3] = ss.w;
        } else {
            longlong2 a = *((const longlong2*)ei + (EE + 4 * e4) / 2);
            longlong2 b = *((const longlong2*)ei + (EE + 4 * e4) / 2 + 1);
            longlong2 c = *((const longlong2*)ei + (4 * e4) / 2);
            longlong2 e = *((const longlong2*)ei + (4 * e4) / 2 + 1);
            d[0] = (int)a.x; d[1] = (int)a.y; d[2] = (int)b.x; d[3] = (int)b.y;
            s[0] = (int)c.x; s[1] = (int)c.y; s[2] = (int)e.x; s[3] = (int)e.y;
        }
        #pragma unroll
        for (int j = 0; j < 4; j++) {
            int pos = atomicAdd(&g_cursor[clampN(d[j])], 1);
            g_srcs[pos] = clampN(s[j]);
        }
    }
}

// ---------------- FP16 tensor-core GEMM primitives --------------------------
__device__ __forceinline__ void mma_fp16(float& c0, float& c1, float& c2, float& c3,
                                         uint32_t a0, uint32_t a1, uint32_t a2, uint32_t a3,
                                         uint32_t b0, uint32_t b1) {
    asm volatile(
        "mma.sync.aligned.m16n8k16.row.col.f32.f16.f16.f32 "
        "{%0,%1,%2,%3},{%4,%5,%6,%7},{%8,%9},{%0,%1,%2,%3};"
        : "+f"(c0), "+f"(c1), "+f"(c2), "+f"(c3)
        : "r"(a0), "r"(a1), "r"(a2), "r"(a3), "r"(b0), "r"(b1));
}

#define LDSM_X4(r0, r1, r2, r3, addr)                                        \
    asm volatile("ldmatrix.sync.aligned.m8n8.x4.shared.b16 {%0,%1,%2,%3}, [%4];" \
                 : "=r"(r0), "=r"(r1), "=r"(r2), "=r"(r3) : "r"(addr))
#define LDSM_X4_T(r0, r1, r2, r3, addr)                                      \
    asm volatile("ldmatrix.sync.aligned.m8n8.x4.trans.shared.b16 {%0,%1,%2,%3}, [%4];" \
                 : "=r"(r0), "=r"(r1), "=r"(r2), "=r"(r3) : "r"(addr))

__device__ __forceinline__ uint2 pack_half4(float4 v) {
    __half2 h01 = __floats2half2_rn(v.x, v.y);
    __half2 h23 = __floats2half2_rn(v.z, v.w);
    uint2 p;
    p.x = *(uint32_t*)&h01;
    p.y = *(uint32_t*)&h23;
    return p;
}

// load a 64x64 A tile into As; Af fp32 XOR Ah fp16 (stride K elements)
__device__ __forceinline__ void load_A_tile(
    const float* __restrict__ Af, const __half* __restrict__ Ah,
    __half (&As)[64][72], int n, int K, int kt, int row0, int tid) {
    if (Ah) {
        // 512 chunks of 8 halves (16B); 2 per thread
        #pragma unroll
        for (int i = 0; i < 2; i++) {
            int idx = i * 256 + tid;
            int r = idx >> 3, c8 = idx & 7;
            uint4 av = make_uint4(0u, 0u, 0u, 0u);
            int gr = row0 + r;
            if (gr < n) av = *(const uint4*)(Ah + (size_t)gr * K + kt + c8 * 8);
            *(uint4*)&As[r][c8 * 8] = av;
        }
    } else {
        #pragma unroll
        for (int i = 0; i < 4; i++) {
            int idx = i * 256 + tid;
            int r = idx >> 4, c4 = idx & 15;
            float4 av = make_float4(0.f, 0.f, 0.f, 0.f);
            int gr = row0 + r;
            if (gr < n) av = *(const float4*)(Af + (size_t)gr * K + kt + c4 * 4);
            *(uint2*)&As[r][c4 * 4] = pack_half4(av);
        }
    }
}

// ---- N=64 tile (8 warps, warp m16n32) — used for gemm_in and s projection --
__device__ __forceinline__ void gemm_tile_fp16(
    const float* __restrict__ Af, const __half* __restrict__ Ah,
    const float* __restrict__ W,
    const float* __restrict__ bias, float* __restrict__ C, __half* __restrict__ Ch,
    int n, int K, int Mw, int Mc, int row0, int colW, int colC) {

    __shared__ __align__(16) __half As[64][72];
    __shared__ __align__(16) __half Bs[64][72];

    int tid  = threadIdx.x;
    int lane = tid & 31;
    int wid  = tid >> 5;
    int wm   = wid & 3;
    int wn   = wid >> 2;
    int g    = lane >> 2;
    int tg   = lane & 3;
    int lrow = (lane < 16) ? lane : lane - 16;
    int lcol = (lane < 16) ? 0 : 8;

    float acc[4][4] = {};

    for (int kt = 0; kt < K; kt += 64) {
        load_A_tile(Af, Ah, As, n, K, kt, row0, tid);
        #pragma unroll
        for (int i = 0; i < 4; i++) {
            int idx = i * 256 + tid;
            int r = idx >> 4, c4 = idx & 15;
            float4 bv = *(const float4*)(W + (size_t)(kt + r) * Mw + colW + c4 * 4);
            *(uint2*)&Bs[r][c4 * 4] = pack_half4(bv);
        }
        __syncthreads();

        #pragma unroll
        for (int ks = 0; ks < 4; ks++) {
            int k0 = ks * 16;
            uint32_t a0, a1, a2, a3;
            uint32_t aaddr = (uint32_t)__cvta_generic_to_shared(
                &As[wm * 16 + lrow][k0 + lcol]);
            LDSM_X4(a0, a1, a2, a3, aaddr);

            uint32_t b00, b01, b10, b11;
            uint32_t baddr0 = (uint32_t)__cvta_generic_to_shared(
                &Bs[k0 + lrow][wn * 32 + lcol]);
            LDSM_X4_T(b00, b01, b10, b11, baddr0);
            uint32_t b20, b21, b30, b31;
            uint32_t baddr1 = (uint32_t)__cvta_generic_to_shared(
                &Bs[k0 + lrow][wn * 32 + 16 + lcol]);
            LDSM_X4_T(b20, b21, b30, b31, baddr1);

            mma_fp16(acc[0][0], acc[0][1], acc[0][2], acc[0][3],
                     a0, a1, a2, a3, b00, b01);
            mma_fp16(acc[1][0], acc[1][1], acc[1][2], acc[1][3],
                     a0, a1, a2, a3, b10, b11);
            mma_fp16(acc[2][0], acc[2][1], acc[2][2], acc[2][3],
                     a0, a1, a2, a3, b20, b21);
            mma_fp16(acc[3][0], acc[3][1], acc[3][2], acc[3][3],
                     a0, a1, a2, a3, b30, b31);
        }
        __syncthreads();
    }

    #pragma unroll
    for (int j = 0; j < 4; j++) {
        int n0 = wn * 32 + j * 8;
        int cw = colW + n0 + tg * 2;
        int cc = colC + n0 + tg * 2;
        float b0 = bias[cw], b1 = bias[cw + 1];
        int r0 = row0 + wm * 16 + g;
        int r1 = r0 + 8;
        if (Ch) {
            if (r0 < n)
                *(__half2*)(Ch + (size_t)r0 * Mc + cc) =
                    __floats2half2_rn(acc[j][0] + b0, acc[j][1] + b1);
            if (r1 < n)
                *(__half2*)(Ch + (size_t)r1 * Mc + cc) =
                    __floats2half2_rn(acc[j][2] + b0, acc[j][3] + b1);
        } else {
            if (r0 < n)
                *(float2*)(C + (size_t)r0 * Mc + cc) =
                    make_float2(acc[j][0] + b0, acc[j][1] + b1);
            if (r1 < n)
                *(float2*)(C + (size_t)r1 * Mc + cc) =
                    make_float2(acc[j][2] + b0, acc[j][3] + b1);
        }
    }
}

// ---- N=128 tile (8 warps, warp m16n64) — q/k/v projections; A fp16, K=64 ---
__device__ __forceinline__ void gemm_tile_fp16_n128(
    const __half* __restrict__ Ah, const float* __restrict__ W,
    const float* __restrict__ bias, __half* __restrict__ Ch,
    int n, int Mw, int Mc, int row0, int colW, int colC) {

    __shared__ __align__(16) __half As[64][72];
    __shared__ __align__(16) __half Bs[64][136];

    int tid  = threadIdx.x;
    int lane = tid & 31;
    int wid  = tid >> 5;
    int wm   = wid & 3;
    int wn   = wid >> 2;
    int g    = lane >> 2;
    int tg   = lane & 3;
    int lrow = (lane < 16) ? lane : lane - 16;
    int lcol = (lane < 16) ? 0 : 8;

    float acc[8][4] = {};

    load_A_tile(nullptr, Ah, As, n, HD, 0, row0, tid);
    #pragma unroll
    for (int i = 0; i < 8; i++) {
        int idx = i * 256 + tid;
        int r = idx >> 5, c4 = idx & 31;
        float4 bv = *(const float4*)(W + (size_t)r * Mw + colW + c4 * 4);
        *(uint2*)&Bs[r][c4 * 4] = pack_half4(bv);
    }
    __syncthreads();

    #pragma unroll
    for (int ks = 0; ks < 4; ks++) {
        int k0 = ks * 16;
        uint32_t a0, a1, a2, a3;
        uint32_t aaddr = (uint32_t)__cvta_generic_to_shared(
            &As[wm * 16 + lrow][k0 + lcol]);
        LDSM_X4(a0, a1, a2, a3, aaddr);

        uint32_t b[16];
        #pragma unroll
        for (int jj = 0; jj < 4; jj++) {
            uint32_t baddr = (uint32_t)__cvta_generic_to_shared(
                &Bs[k0 + lrow][wn * 64 + jj * 16 + lcol]);
            LDSM_X4_T(b[jj * 4], b[jj * 4 + 1], b[jj * 4 + 2], b[jj * 4 + 3], baddr);
        }
        #pragma unroll
        for (int jf = 0; jf < 8; jf++) {
            mma_fp16(acc[jf][0], acc[jf][1], acc[jf][2], acc[jf][3],
                     a0, a1, a2, a3, b[jf * 2], b[jf * 2 + 1]);
        }
    }

    #pragma unroll
    for (int j = 0; j < 8; j++) {
        int n0 = wn * 64 + j * 8;
        int cw = colW + n0 + tg * 2;
        int cc = colC + n0 + tg * 2;
        float b0 = bias[cw], b1 = bias[cw + 1];
        int r0 = row0 + wm * 16 + g;
        int r1 = r0 + 8;
        if (r0 < n)
            *(__half2*)(Ch + (size_t)r0 * Mc + cc) =
                __floats2half2_rn(acc[j][0] + b0, acc[j][1] + b1);
        if (r1 < n)
            *(__half2*)(Ch + (size_t)r1 * Mc + cc) =
                __floats2half2_rn(acc[j][2] + b0, acc[j][3] + b1);
    }
}

__global__ __launch_bounds__(256) void k_gemm_in(const float* __restrict__ x,
                                                 const float* __restrict__ W,
                                                 const float* __restrict__ bias) {
    gemm_tile_fp16(x, nullptr, W, bias, nullptr, g_h0, NN, IND, HD, HD,
                   blockIdx.x * 64, 0, 0);
}

// fused q/k/v/s: grid.y = 7 (0-1 q, 2-3 k, 4-5 v [N=128 tiles], 6 s [N=64])
__global__ __launch_bounds__(256) void k_gemm_qkvs(int a_sel,
        const float* __restrict__ Wq, const float* __restrict__ bq,
        const float* __restrict__ Wk, const float* __restrict__ bk,
        const float* __restrict__ Wv, const float* __restrict__ bv,
        const float* __restrict__ Ws, const float* __restrict__ bs) {
    const __half* A = buf_sel(a_sel);
    int ct = blockIdx.y;
    if (ct == 6) {
        gemm_tile_fp16(nullptr, A, Ws, bs, g_s, nullptr, NN, HD, HD, HD,
                       blockIdx.x * 64, 0, 0);
        return;
    }
    const float* W; const float* bias; __half* Ch; int col;
    if (ct < 2)       { W = Wq; bias = bq; Ch = g_qh; col = ct * 128; }
    else if (ct < 4)  { W = Wk; bias = bk; Ch = g_kh; col = (ct - 2) * 128; }
    else              { W = Wv; bias = bv; Ch = g_vh; col = (ct - 4) * 128; }
    gemm_tile_fp16_n128(A, W, bias, Ch, NN, QKVD, QKVD,
                        blockIdx.x * 64, col, col);
}

// ---------------- per-node attention: single-pass online softmax ------------
// one warp per node; lane = head*8 + t; lane owns 8 contiguous fp16 columns.
// (R14-validated lean form — q now fp16, converted once per node.)
__global__ void k_attn(int out_sel) {
    int node = (blockIdx.x * blockDim.x + threadIdx.x) >> 5;
    if (node >= NN) return;
    __half* hout = buf_sel(out_sel);
    int lane = threadIdx.x & 31;
    int h = lane >> 3, t = lane & 7;
    int col = h * 64 + t * 8;

    uint4 qw = *(const uint4*)(g_qh + (size_t)node * QKVD + col);
    const __half2* qh2 = (const __half2*)&qw;
    float2 q0 = __half22float2(qh2[0]);
    float2 q1 = __half22float2(qh2[1]);
    float2 q2 = __half22float2(qh2[2]);
    float2 q3 = __half22float2(qh2[3]);
    float4 qa = make_float4(q0.x, q0.y, q1.x, q1.y);
    float4 qb = make_float4(q2.x, q2.y, q3.x, q3.y);

    int beg = g_rowptr[node], end = g_rowptr[node + 1];

    float m = -1e30f, denom = 0.f;
    float acc[8] = {0.f, 0.f, 0.f, 0.f, 0.f, 0.f, 0.f, 0.f};

    uint4 kw, vw;
    if (beg < end) {
        int s0 = g_srcs[beg];
        kw = *(const uint4*)(g_kh + (size_t)s0 * QKVD + col);
        vw = *(const uint4*)(g_vh + (size_t)s0 * QKVD + col);
    }

    for (int p = beg; p < end; ++p) {
        uint4 kc = kw, vc = vw;
        if (p + 1 < end) {
            int s1 = g_srcs[p + 1];
            kw = *(const uint4*)(g_kh + (size_t)s1 * QKVD + col);
            vw = *(const uint4*)(g_vh + (size_t)s1 * QKVD + col);
        }

        const __half2* kh = (const __half2*)&kc;
        float2 k0 = __half22float2(kh[0]);
        float2 k1 = __half22float2(kh[1]);
        float2 k2 = __half22float2(kh[2]);
        float2 k3 = __half22float2(kh[3]);

        float d = qa.x * k0.x + qa.y * k0.y + qa.z * k1.x + qa.w * k1.y
                + qb.x * k2.x + qb.y * k2.y + qb.z * k3.x + qb.w * k3.y;
        d += __shfl_xor_sync(0xffffffffu, d, 1);
        d += __shfl_xor_sync(0xffffffffu, d, 2);
        d += __shfl_xor_sync(0xffffffffu, d, 4);
        d *= 0.125f;                       // 1/sqrt(64)

        float nm   = fmaxf(m, d);
        float corr = __expf(m - nm);
        float ex   = __expf(d - nm);
        m = nm;
        denom = denom * corr + ex;

        const __half2* vh = (const __half2*)&vc;
        float2 v0 = __half22float2(vh[0]);
        float2 v1 = __half22float2(vh[1]);
        float2 v2 = __half22float2(vh[2]);
        float2 v3 = __half22float2(vh[3]);
        acc[0] = acc[0] * corr + ex * v0.x;
        acc[1] = acc[1] * corr + ex * v0.y;
        acc[2] = acc[2] * corr + ex * v1.x;
        acc[3] = acc[3] * corr + ex * v1.y;
        acc[4] = acc[4] * corr + ex * v2.x;
        acc[5] = acc[5] * corr + ex * v2.y;
        acc[6] = acc[6] * corr + ex * v3.x;
        acc[7] = acc[7] * corr + ex * v3.y;
    }
    float inv = denom > 0.f ? 1.f / denom : 0.f;

    #pragma unroll
    for (int j = 0; j < 8; j++) {
        float o = acc[j] * inv;
        o += __shfl_xor_sync(0xffffffffu, o, 8);
        o += __shfl_xor_sync(0xffffffffu, o, 16);
        acc[j] = o;
    }

    if (h == 0) {
        const float* sp = g_s + (size_t)node * HD + t * 8;
        float v[8];
        #pragma unroll
        for (int j = 0; j < 8; j++)
            v[j] = fmaxf(0.25f * acc[j] + sp[j], 0.f);   // head mean + skip + ReLU
        uint4 o;
        __half2 p0 = __floats2half2_rn(v[0], v[1]);
        __half2 p1 = __floats2half2_rn(v[2], v[3]);
        __half2 p2 = __floats2half2_rn(v[4], v[5]);
        __half2 p3 = __floats2half2_rn(v[6], v[7]);
        o.x = *(uint32_t*)&p0;
        o.y = *(uint32_t*)&p1;
        o.z = *(uint32_t*)&p2;
        o.w = *(uint32_t*)&p3;
        *(uint4*)(hout + (size_t)node * HD + t * 8) = o;
    }
}

// ---------------- global add pool -------------------------------------------
__global__ void k_pool_zero(float* out) {
    int i = blockIdx.x * blockDim.x + threadIdx.x;
    if (i < NG * HD) out[i] = 0.f;
}

__global__ void k_pool(int in_sel, const void* __restrict__ batch,
                       float* out) {
    const __half* hh = buf_sel(in_sel);
    int i = blockIdx.x * blockDim.x + threadIdx.x;
    if (i < NN * HD) {
        int row = i >> 6;
        int g = g_use32 ? ((const int*)batch)[row]
                        : (int)((const long long*)batch)[row];
        g = g < 0 ? 0 : (g >= NG ? NG - 1 : g);
        atomicAdd(&out[g * HD + (i & 63)], __half2float(hh[i]));
    }
}

// ---------------- host ------------------------------------------------------
extern "C" void kernel_launch(void* const* d_in, const int* in_sizes, int n_in,
                              void* d_out, int out_size) {
    (void)in_sizes; (void)n_in; (void)out_size;
    const float* x     = (const float*)d_in[0];
    const void*  ei    = d_in[1];
    const void*  batch = d_in[2];
    const float* lin_W = (const float*)d_in[3];
    const float* lin_b = (const float*)d_in[4];
    const float* Wq = (const float*)d_in[5];
    const float* bq = (const float*)d_in[6];
    const float* Wk = (const float*)d_in[7];
    const float* bk = (const float*)d_in[8];
    const float* Wv = (const float*)d_in[9];
    const float* bv = (const float*)d_in[10];
    const float* Ws = (const float*)d_in[11];
    const float* bs = (const float*)d_in[12];

    // side stream for CSR build + output zeroing (fork/join, capture-legal)
    cudaStream_t s2;
    cudaStreamCreateWithFlags(&s2, cudaStreamNonBlocking);
    cudaEvent_t eFork, eJoin;
    cudaEventCreateWithFlags(&eFork, cudaEventDisableTiming);
    cudaEventCreateWithFlags(&eJoin, cudaEventDisableTiming);

    cudaEventRecord(eFork, 0);
    cudaStreamWaitEvent(s2, eFork, 0);

    k_pool_zero<<<(NG * HD + 255) / 256, 256, 0, s2>>>((float*)d_out);
    k_detect<<<1, 32, 0, s2>>>(ei);
    k_zero_cnt<<<(NN + 255) / 256, 256, 0, s2>>>();
    k_count<<<(EE / 4 + 255) / 256, 256, 0, s2>>>(ei);
    k_scan1<<<NB, 256, 0, s2>>>();
    k_scan2<<<1, 128, 0, s2>>>();
    k_scan3<<<NB, 256, 0, s2>>>();
    k_scatter<<<(EE / 4 + 255) / 256, 256, 0, s2>>>(ei);
    cudaEventRecord(eJoin, s2);

    const int RT = (NN + 63) / 64;  // 313 row tiles

    k_gemm_in<<<dim3(RT, 1), 256>>>(x, lin_W, lin_b);

    int hin = 0, hou = 1;
    for (int l = 0; l < NL; l++) {
        k_gemm_qkvs<<<dim3(RT, 7), 256>>>(hin,
            Wq + (size_t)l * HD * QKVD, bq + (size_t)l * QKVD,
            Wk + (size_t)l * HD * QKVD, bk + (size_t)l * QKVD,
            Wv + (size_t)l * HD * QKVD, bv + (size_t)l * QKVD,
            Ws + (size_t)l * HD * HD,   bs + (size_t)l * HD);
        if (l == 0) cudaStreamWaitEvent(0, eJoin, 0);   // CSR + zeroed out ready
        k_attn<<<(NN * 32 + 255) / 256, 256>>>(hou);
        int tmp = hin; hin = hou; hou = tmp;
    }

    k_pool<<<(NN * HD + 255) / 256, 256>>>(hin, batch, (float*)d_out);
}